// round 16
// baseline (speedup 1.0000x reference)
#include <cuda_runtime.h>
#include <float.h>
#include <math.h>

// ---------------- problem constants ----------------
#define NMAX   16000
#define NGRAPH 16
#define NPG    1000          // nodes per graph
#define KNN    20
#define HDIM   64
#define LAYERS 4

typedef unsigned long long ull;

// ---------------- device scratch (no allocations allowed) ----------------
__device__ float g_hbuf[2][NMAX * HDIM];   // ping-pong node features (fp32)
__device__ float g_s64[NMAX * HDIM];       // prefix chain: x_i over W rows 0..63 (NO bias)
__device__ float g_sq[NMAX];               // ||h_i||^2, scalar-serial (XLA-CPU order)
__device__ float g_d2[NGRAPH * NPG * NPG]; // per-graph distance matrices (64MB)

__device__ __forceinline__ float eluf(float x) {
    return x > 0.0f ? x : expm1f(x);
}

// monotone u32 transform: bitwise order == float order (-0.0 cannot occur in d2)
__device__ __forceinline__ unsigned mono32(float v) {
    unsigned u = __float_as_uint(v);
    return (u & 0x80000000u) ? ~u : (u | 0x80000000u);
}

// ---------------- lc_encode: x[N,8] -> h[N,64], 32 nodes/block, weights in smem ----------------
__global__ void lc_kernel(const float* __restrict__ x,
                          const float* __restrict__ W1, const float* __restrict__ b1,
                          const float* __restrict__ W2, const float* __restrict__ b2) {
    __shared__ float sW1[8 * 32], sW2[32 * 64];
    __shared__ float sb1[32], sb2[64];
    __shared__ float sx[32][9];
    __shared__ float sh1[32][33];
    int tid = threadIdx.x;                 // 256
    int i0 = blockIdx.x * 32;

    sW1[tid] = W1[tid];
    for (int t = tid; t < 32 * 64; t += 256) sW2[t] = W2[t];
    if (tid < 32) sb1[tid] = b1[tid];
    if (tid < 64) sb2[tid] = b2[tid];
    sx[tid >> 3][tid & 7] = x[(i0 + (tid >> 3)) * 8 + (tid & 7)];
    __syncthreads();

    int node = tid >> 3, slot = tid & 7;
#pragma unroll
    for (int oo = 0; oo < 4; oo++) {
        int o = slot * 4 + oo;
        float s = 0.0f;
#pragma unroll
        for (int e = 0; e < 8; e++) s = __fmaf_rn(sx[node][e], sW1[e * 32 + o], s);
        sh1[node][o] = eluf(__fadd_rn(s, sb1[o]));
    }
    __syncthreads();
#pragma unroll
    for (int oo = 0; oo < 8; oo++) {
        int o = slot * 8 + oo;
        float s = 0.0f;
#pragma unroll
        for (int e = 0; e < 32; e++) s = __fmaf_rn(sh1[node][e], sW2[e * 64 + o], s);
        g_hbuf[0][(i0 + node) * 64 + o] = eluf(__fadd_rn(s, sb2[o]));
    }
}

// ---------------- ac + sq fused (bitwise frozen chains) ----------------
__global__ void ac_kernel(int src, const float* __restrict__ convW, int l) {
    int tid = threadIdx.x;                 // 256
    int nl = tid >> 6, d = tid & 63;
    int i = blockIdx.x * 4 + nl;
    const float* Hh = g_hbuf[src];
    __shared__ float hs[4][64];
    hs[nl][d] = Hh[i * 64 + d];
    __syncthreads();
    const float* W = convW + l * 128 * 64;
    float a = 0.0f;
#pragma unroll 8
    for (int e = 0; e < 64; e++)
        a = __fmaf_rn(hs[nl][e], W[e * 64 + d], a);
    g_s64[i * 64 + d] = a;
    if (tid < 4) {
        float acc = 0.0f;
#pragma unroll 8
        for (int k = 0; k < 64; k++) {
            float v = hs[tid][k];
            acc = __fadd_rn(acc, __fmul_rn(v, v));
        }
        g_sq[blockIdx.x * 4 + tid] = acc;
    }
}

// ---------------- pairwise distance: d2 = sub(add(sq_i,sq_j), mul(2,dot)) ----------------
#define TM 128
#define KC 32
#define NTILE 8
#define NPAIRS (NTILE * (NTILE + 1) / 2)     // 36
__global__ void __launch_bounds__(512, 2) dist_kernel(int src) {
    const float* Hh = g_hbuf[src];
    int g = blockIdx.z;
    int idx = blockIdx.x;
    int ti = (int)((sqrtf(8.0f * (float)idx + 1.0f) - 1.0f) * 0.5f);
    while ((ti + 1) * (ti + 2) / 2 <= idx) ti++;
    while (ti * (ti + 1) / 2 > idx) ti--;
    int tj = idx - ti * (ti + 1) / 2;

    int i0 = ti * TM;
    int j0 = tj * TM;
    int base = g * NPG;
    __shared__ __align__(16) float His[KC][TM + 4];   // 4224 floats
    __shared__ __align__(16) float Hjs[KC][TM + 4];
    int tid = threadIdx.x;           // 512 threads
    int tx = tid & 31, ty = tid >> 5;
    float acc[8][4];
#pragma unroll
    for (int a = 0; a < 8; a++)
#pragma unroll
        for (int b = 0; b < 4; b++) acc[a][b] = 0.0f;

    for (int kc = 0; kc < HDIM; kc += KC) {
        __syncthreads();
        for (int t = tid; t < TM * KC; t += 512) {
            int node = t >> 5;
            int k = t & 31;
            int gi = i0 + node;
            His[k][node] = (gi < NPG) ? Hh[(base + gi) * 64 + kc + k] : 0.0f;
            int gj = j0 + node;
            Hjs[k][node] = (gj < NPG) ? Hh[(base + gj) * 64 + kc + k] : 0.0f;
        }
        __syncthreads();
#pragma unroll
        for (int k = 0; k < KC; k++) {
            float av[8], bv[4];
            *(float4*)&av[0] = *(const float4*)&His[k][ty * 8];
            *(float4*)&av[4] = *(const float4*)&His[k][ty * 8 + 4];
            *(float4*)&bv[0] = *(const float4*)&Hjs[k][tx * 4];
#pragma unroll
            for (int a = 0; a < 8; a++)
#pragma unroll
                for (int b = 0; b < 4; b++)
                    acc[a][b] = __fmaf_rn(av[a], bv[b], acc[a][b]);
        }
    }

    float si[8], sj[4];
#pragma unroll
    for (int a = 0; a < 8; a++) {
        int gi = i0 + ty * 8 + a;
        si[a] = (gi < NPG) ? g_sq[base + gi] : 0.0f;
    }
#pragma unroll
    for (int b = 0; b < 4; b++) {
        int gj = j0 + tx * 4 + b;
        sj[b] = (gj < NPG) ? g_sq[base + gj] : 0.0f;
    }

    float* d2g = g_d2 + (size_t)g * NPG * NPG;
#pragma unroll
    for (int a = 0; a < 8; a++) {
        int gi = i0 + ty * 8 + a;
        if (gi >= NPG) continue;
        int gj0 = j0 + tx * 4;
        float v0 = __fsub_rn(__fadd_rn(si[a], sj[0]), __fmul_rn(2.0f, acc[a][0]));
        float v1 = __fsub_rn(__fadd_rn(si[a], sj[1]), __fmul_rn(2.0f, acc[a][1]));
        float v2 = __fsub_rn(__fadd_rn(si[a], sj[2]), __fmul_rn(2.0f, acc[a][2]));
        float v3 = __fsub_rn(__fadd_rn(si[a], sj[3]), __fmul_rn(2.0f, acc[a][3]));
        if (gj0 + 3 < NPG) {
            float4 vv = make_float4(v0, v1, v2, v3);
            *(float4*)&d2g[gi * NPG + gj0] = vv;
        } else {
            if (gj0     < NPG) d2g[gi * NPG + gj0]     = v0;
            if (gj0 + 1 < NPG) d2g[gi * NPG + gj0 + 1] = v1;
            if (gj0 + 2 < NPG) d2g[gi * NPG + gj0 + 2] = v2;
            if (gj0 + 3 < NPG) d2g[gi * NPG + gj0 + 3] = v3;
        }
    }

    if (ti != tj) {
        float* Tr = &His[0][0];            // [128][33]
#pragma unroll 1
        for (int c = 0; c < 4; c++) {
            __syncthreads();
            if ((ty >> 2) == c) {
#pragma unroll
                for (int a = 0; a < 8; a++) {
                    int il = (ty * 8 + a) & 31;
#pragma unroll
                    for (int b = 0; b < 4; b++) {
                        float v = __fsub_rn(__fadd_rn(si[a], sj[b]), __fmul_rn(2.0f, acc[a][b]));
                        Tr[(tx * 4 + b) * 33 + il] = v;
                    }
                }
            }
            __syncthreads();
            for (int t = tid; t < 128 * 32; t += 512) {
                int jr = t >> 5, ic = t & 31;
                int gj = j0 + jr, gi = i0 + c * 32 + ic;
                if (gj < NPG && gi < NPG)
                    d2g[(size_t)gj * NPG + gi] = Tr[jr * 33 + ic];
            }
        }
    }
}

// ---------------- fused knn (register + redux) + edge MLP + BN + max aggr + residual ----------------
// Phase A: candidates in registers (lane holds j = 128q + 4*lane + r at c = 4q+r;
//          ascending c == ascending j per lane). Per extraction: redux-min on keys,
//          tied lanes propose lowest-j, redux-min on j -> winner clears + rescans.
//          Lexicographic (key, j) min: identical selection semantics, d2 bits untouched.
//          Winner index `it` is kept in lane it's register (no idxs smem).
// Phase B: edge-MLP with bitwise-frozen serial ascending-k chains + exact BN order.
//          WbT staged to smem with loads ISSUED BEFORE Phase A (latency hidden).
__global__ void __launch_bounds__(128) agg_kernel(int src, const float* __restrict__ convW,
                           const float* __restrict__ convb,
                           const float* __restrict__ bn_g, const float* __restrict__ bn_b,
                           const float* __restrict__ bn_m, const float* __restrict__ bn_v,
                           int l) {
    __shared__ __align__(16) float WbT[64][68];          // WbT[d][k] = W[(64+k)*64+d]
    __shared__ __align__(16) float diff[4][KNN][64];

    int tid = threadIdx.x;                 // 128
    int nl = tid >> 5, lane = tid & 31;
    int i = blockIdx.x * 4 + nl;
    int g = i / NPG, il = i % NPG;
    const float* Hh = g_hbuf[src];
    float* hdst = g_hbuf[src ^ 1];
    const float* W = convW + l * 128 * 64;

    // stage WbT (loads issued now; latency hides under Phase A)
    for (int t = tid; t < 4096; t += 128) {
        int k = t >> 6, d = t & 63;
        WbT[d][k] = W[(64 + k) * 64 + d];
    }

    // ================= Phase A: kNN selection (register-resident) =================
    int myidx = 0;     // lane `it` ends up holding winner #it (global node index)
    {
        const float* row = g_d2 + (size_t)g * NPG * NPG + (size_t)il * NPG;
        unsigned v[32];
#pragma unroll
        for (int q = 0; q < 8; q++) {
            int j = q * 128 + lane * 4;
            float4 r4;
            if (j + 3 < NPG) {
                r4 = *(const float4*)&row[j];
            } else {
                r4.x = (j     < NPG) ? row[j]     : 0.0f;
                r4.y = (j + 1 < NPG) ? row[j + 1] : 0.0f;
                r4.z = (j + 2 < NPG) ? row[j + 2] : 0.0f;
                r4.w = (j + 3 < NPG) ? row[j + 3] : 0.0f;
            }
            v[q * 4 + 0] = (j     < NPG) ? mono32(r4.x) : 0xFFFFFFFFu;
            v[q * 4 + 1] = (j + 1 < NPG) ? mono32(r4.y) : 0xFFFFFFFFu;
            v[q * 4 + 2] = (j + 2 < NPG) ? mono32(r4.z) : 0xFFFFFFFFu;
            v[q * 4 + 3] = (j + 3 < NPG) ? mono32(r4.w) : 0xFFFFFFFFu;
        }
        // per-lane argmin (strict < keeps lowest c == lowest j)
        unsigned lmin = v[0];
        int lminc = 0;
#pragma unroll
        for (int c = 1; c < 32; c++)
            if (v[c] < lmin) { lmin = v[c]; lminc = c; }

        for (int it = 0; it < KNN; it++) {
            unsigned m = __reduce_min_sync(0xFFFFFFFFu, lmin);
            int jc = (lmin == m) ? ((lminc >> 2) * 128 + lane * 4 + (lminc & 3))
                                 : 0x7FFFFFFF;
            int jw = __reduce_min_sync(0xFFFFFFFFu, (unsigned)jc);
            if (lane == it) myidx = g * NPG + jw;
            if (jc == jw) {
#pragma unroll
                for (int c = 0; c < 32; c++)
                    v[c] = (c == lminc) ? 0xFFFFFFFFu : v[c];
                lmin = v[0]; lminc = 0;
#pragma unroll
                for (int c = 1; c < 32; c++)
                    if (v[c] < lmin) { lmin = v[c]; lminc = c; }
            }
        }
    }
    __syncthreads();   // WbT staging complete across all warps

    // ================= Phase B: edge MLP (bitwise-frozen chains) =================
    float xi0 = Hh[i * 64 + lane];
    float xi1 = Hh[i * 64 + lane + 32];

#pragma unroll
    for (int nb = 0; nb < KNN; nb++) {
        int jn = __shfl_sync(0xFFFFFFFFu, myidx, nb);
        const float* hj = Hh + jn * 64;
        diff[nl][nb][lane]      = __fsub_rn(hj[lane],      xi0);
        diff[nl][nb][lane + 32] = __fsub_rn(hj[lane + 32], xi1);
    }
    __syncwarp();

    float s0 = g_s64[i * 64 + lane];
    float s1 = g_s64[i * 64 + lane + 32];
    float acc0[KNN], acc1[KNN];
#pragma unroll
    for (int nb = 0; nb < KNN; nb++) { acc0[nb] = s0; acc1[nb] = s1; }

#pragma unroll 2
    for (int k4 = 0; k4 < 16; k4++) {
        float4 w0q = *(const float4*)&WbT[lane][k4 * 4];
        float4 w1q = *(const float4*)&WbT[lane + 32][k4 * 4];
#pragma unroll
        for (int nb = 0; nb < KNN; nb++) {
            float4 d4 = *(const float4*)&diff[nl][nb][k4 * 4];
            acc0[nb] = __fmaf_rn(d4.x, w0q.x, acc0[nb]);
            acc0[nb] = __fmaf_rn(d4.y, w0q.y, acc0[nb]);
            acc0[nb] = __fmaf_rn(d4.z, w0q.z, acc0[nb]);
            acc0[nb] = __fmaf_rn(d4.w, w0q.w, acc0[nb]);
            acc1[nb] = __fmaf_rn(d4.x, w1q.x, acc1[nb]);
            acc1[nb] = __fmaf_rn(d4.y, w1q.y, acc1[nb]);
            acc1[nb] = __fmaf_rn(d4.z, w1q.z, acc1[nb]);
            acc1[nb] = __fmaf_rn(d4.w, w1q.w, acc1[nb]);
        }
    }

    float bi0 = convb[l * 64 + lane],  bi1 = convb[l * 64 + lane + 32];
    float mm0 = bn_m[l * 64 + lane],   mm1 = bn_m[l * 64 + lane + 32];
    float bb0 = bn_b[l * 64 + lane],   bb1 = bn_b[l * 64 + lane + 32];
    float gg0 = bn_g[l * 64 + lane],   gg1 = bn_g[l * 64 + lane + 32];
    float rr0 = __fdiv_rn(1.0f, __fsqrt_rn(__fadd_rn(bn_v[l * 64 + lane],      1e-5f)));
    float rr1 = __fdiv_rn(1.0f, __fsqrt_rn(__fadd_rn(bn_v[l * 64 + lane + 32], 1e-5f)));
    float best0 = -FLT_MAX, best1 = -FLT_MAX;
#pragma unroll
    for (int nb = 0; nb < KNN; nb++) {
        float e0 = eluf(__fadd_rn(acc0[nb], bi0));
        float e1 = eluf(__fadd_rn(acc1[nb], bi1));
        float v0 = __fadd_rn(__fmul_rn(__fmul_rn(gg0, __fsub_rn(e0, mm0)), rr0), bb0);
        float v1 = __fadd_rn(__fmul_rn(__fmul_rn(gg1, __fsub_rn(e1, mm1)), rr1), bb1);
        best0 = fmaxf(best0, v0);
        best1 = fmaxf(best1, v1);
    }
    hdst[i * 64 + lane]      = __fadd_rn(best0, xi0);
    hdst[i * 64 + lane + 32] = __fadd_rn(best1, xi1);
}

// ---------------- output heads: 32 nodes/block, weights staged in smem ----------------
__global__ void heads_kernel(int src,
                             const float* __restrict__ oW1, const float* __restrict__ ob1,
                             const float* __restrict__ oW2, const float* __restrict__ ob2,
                             const float* __restrict__ oW3, const float* __restrict__ ob3,
                             const float* __restrict__ spW1, const float* __restrict__ spb1,
                             const float* __restrict__ spW2, const float* __restrict__ spb2,
                             const float* __restrict__ spW3, const float* __restrict__ spb3,
                             float* __restrict__ out, int out_size, int N) {
    __shared__ float sW1[64 * 64], sW2[64 * 32], sW3[32 * 8];
    __shared__ float sb1v[64], sb2v[32], sb3v[8];
    __shared__ float hr[32][65], t1[32][65], t2[32][33];
    int tid = threadIdx.x;               // 256
    int i0 = blockIdx.x * 32;
    const float* Hh = g_hbuf[src];

    for (int t = tid; t < 32 * 64; t += 256)
        hr[t >> 6][t & 63] = Hh[(i0 + (t >> 6)) * 64 + (t & 63)];

    int node = tid >> 3, slot = tid & 7;

    for (int head = 0; head < 2; head++) {
        const float* w1 = head == 0 ? oW1 : spW1;
        const float* w2 = head == 0 ? oW2 : spW2;
        const float* w3 = head == 0 ? oW3 : spW3;
        const float* c1 = head == 0 ? ob1 : spb1;
        const float* c2 = head == 0 ? ob2 : spb2;
        const float* c3 = head == 0 ? ob3 : spb3;
        int w3n = head == 0 ? 256 : 32;

        for (int t = tid; t < 4096; t += 256) sW1[t] = w1[t];
        for (int t = tid; t < 2048; t += 256) sW2[t] = w2[t];
        if (tid < 256 && tid < w3n) sW3[tid] = w3[tid];
        if (tid < 64) sb1v[tid] = c1[tid];
        if (tid < 32) sb2v[tid] = c2[tid];
        if (tid < 8)  sb3v[tid] = (head == 0) ? c3[tid] : (tid == 0 ? c3[0] : 0.0f);
        __syncthreads();

#pragma unroll
        for (int oo = 0; oo < 8; oo++) {
            int o = slot * 8 + oo;
            float s = 0.0f;
#pragma unroll 8
            for (int e = 0; e < 64; e++) s = __fmaf_rn(hr[node][e], sW1[e * 64 + o], s);
            t1[node][o] = eluf(__fadd_rn(s, sb1v[o]));
        }
        __syncthreads();
#pragma unroll
        for (int oo = 0; oo < 4; oo++) {
            int o = slot * 4 + oo;
            float s = 0.0f;
#pragma unroll 8
            for (int e = 0; e < 64; e++) s = __fmaf_rn(t1[node][e], sW2[e * 32 + o], s);
            t2[node][o] = eluf(__fadd_rn(s, sb2v[o]));
        }
        __syncthreads();
        if (head == 0) {
            int o = slot;
            float s = 0.0f;
#pragma unroll
            for (int e = 0; e < 32; e++) s = __fmaf_rn(t2[node][e], sW3[e * 8 + o], s);
            out[(i0 + node) * 8 + o] = __fadd_rn(s, sb3v[o]);
        } else {
            if (slot == 0) {
                float s = 0.0f;
#pragma unroll
                for (int e = 0; e < 32; e++) s = __fmaf_rn(t2[node][e], sW3[e], s);
                s = __fadd_rn(s, sb3v[0]);
                int i = i0 + node;
                int off_sp = N * 8;
                if (off_sp + i < out_size) out[off_sp + i] = s;
                int off_b = N * 9;
                if (off_b + i < out_size) out[off_b + i] = (float)(i / NPG);
            }
        }
        __syncthreads();
    }
}

// ---------------- host launcher ----------------
extern "C" void kernel_launch(void* const* d_in, const int* in_sizes, int n_in,
                              void* d_out, int out_size) {
    const float* x     = (const float*)d_in[0];
    const float* lcW1  = (const float*)d_in[2];
    const float* lcb1  = (const float*)d_in[3];
    const float* lcW2  = (const float*)d_in[4];
    const float* lcb2  = (const float*)d_in[5];
    const float* convW = (const float*)d_in[6];
    const float* convb = (const float*)d_in[7];
    const float* bn_g  = (const float*)d_in[8];
    const float* bn_b  = (const float*)d_in[9];
    const float* bn_m  = (const float*)d_in[10];
    const float* bn_v  = (const float*)d_in[11];
    const float* outW1 = (const float*)d_in[12];
    const float* outb1 = (const float*)d_in[13];
    const float* outW2 = (const float*)d_in[14];
    const float* outb2 = (const float*)d_in[15];
    const float* outW3 = (const float*)d_in[16];
    const float* outb3 = (const float*)d_in[17];
    const float* spW1  = (const float*)d_in[18];
    const float* spb1  = (const float*)d_in[19];
    const float* spW2  = (const float*)d_in[20];
    const float* spb2  = (const float*)d_in[21];
    const float* spW3  = (const float*)d_in[22];
    const float* spb3  = (const float*)d_in[23];

    const int N = in_sizes[0] / 8;          // 16000

    lc_kernel<<<N / 32, 256>>>(x, lcW1, lcb1, lcW2, lcb2);

    int src = 0;
    for (int l = 0; l < LAYERS; l++) {
        ac_kernel<<<N / 4, 256>>>(src, convW, l);
        dist_kernel<<<dim3(NPAIRS, 1, NGRAPH), 512>>>(src);
        agg_kernel<<<N / 4, 128>>>(src, convW, convb, bn_g, bn_b, bn_m, bn_v, l);
        src ^= 1;
    }

    heads_kernel<<<N / 32, 256>>>(src, outW1, outb1, outW2, outb2, outW3, outb3,
                                  spW1, spb1, spW2, spb2, spW3, spb3,
                                  (float*)d_out, out_size, N);
}

// round 17
// speedup vs baseline: 1.1883x; 1.1883x over previous
#include <cuda_runtime.h>
#include <float.h>
#include <math.h>

// ---------------- problem constants ----------------
#define NMAX   16000
#define NGRAPH 16
#define NPG    1000          // nodes per graph
#define KNN    20
#define HDIM   64
#define LAYERS 4

typedef unsigned long long ull;

// ---------------- device scratch (no allocations allowed) ----------------
__device__ float g_hbuf[2][NMAX * HDIM];   // ping-pong node features (fp32)
__device__ float g_s64[NMAX * HDIM];       // prefix chain: x_i over W rows 0..63 (NO bias)
__device__ float g_d2[NGRAPH * NPG * NPG]; // per-graph distance matrices (64MB)

__device__ __forceinline__ float eluf(float x) {
    return x > 0.0f ? x : expm1f(x);
}

// monotone u32 transform: bitwise order == float order (-0.0 cannot occur in d2)
__device__ __forceinline__ unsigned mono32(float v) {
    unsigned u = __float_as_uint(v);
    return (u & 0x80000000u) ? ~u : (u | 0x80000000u);
}

// ---------------- lc_encode: x[N,8] -> h[N,64], 32 nodes/block, weights in smem ----------------
__global__ void lc_kernel(const float* __restrict__ x,
                          const float* __restrict__ W1, const float* __restrict__ b1,
                          const float* __restrict__ W2, const float* __restrict__ b2) {
    __shared__ float sW1[8 * 32], sW2[32 * 64];
    __shared__ float sb1[32], sb2[64];
    __shared__ float sx[32][9];
    __shared__ float sh1[32][33];
    int tid = threadIdx.x;                 // 256
    int i0 = blockIdx.x * 32;

    sW1[tid] = W1[tid];
    for (int t = tid; t < 32 * 64; t += 256) sW2[t] = W2[t];
    if (tid < 32) sb1[tid] = b1[tid];
    if (tid < 64) sb2[tid] = b2[tid];
    sx[tid >> 3][tid & 7] = x[(i0 + (tid >> 3)) * 8 + (tid & 7)];
    __syncthreads();

    int node = tid >> 3, slot = tid & 7;
#pragma unroll
    for (int oo = 0; oo < 4; oo++) {
        int o = slot * 4 + oo;
        float s = 0.0f;
#pragma unroll
        for (int e = 0; e < 8; e++) s = __fmaf_rn(sx[node][e], sW1[e * 32 + o], s);
        sh1[node][o] = eluf(__fadd_rn(s, sb1[o]));
    }
    __syncthreads();
#pragma unroll
    for (int oo = 0; oo < 8; oo++) {
        int o = slot * 8 + oo;
        float s = 0.0f;
#pragma unroll
        for (int e = 0; e < 32; e++) s = __fmaf_rn(sh1[node][e], sW2[e * 64 + o], s);
        g_hbuf[0][(i0 + node) * 64 + o] = eluf(__fadd_rn(s, sb2[o]));
    }
}

// ---------------- fused dist + ac kernel ----------------
// blocks [0, NGRAPH*NPAIRS): distance tiles; d2 = sub(add(sq_i,sq_j), mul(2,dot)).
//   sq computed IN-BLOCK from smem tiles with the frozen scalar-serial add(mul)
//   chain (k ascending across chunks == global ascending order) -> bitwise identical.
// blocks [NGRAPH*NPAIRS, +N/8): ac path; s64 = serial ascending chain of x_i over
//   W rows 0..63 (NO bias) [bitwise frozen]. Independent of dist blocks.
#define TM 128
#define KC 32
#define NTILE 8
#define NPAIRS (NTILE * (NTILE + 1) / 2)     // 36
#define DIST_BLOCKS (NGRAPH * NPAIRS)        // 576
__global__ void __launch_bounds__(512, 2) dist_ac_kernel(int src,
                                                         const float* __restrict__ convW,
                                                         int l) {
    __shared__ __align__(16) float His[KC][TM + 4];   // 4224 floats
    __shared__ __align__(16) float Hjs[KC][TM + 4];
    __shared__ float sqi[TM], sqj[TM];

    const float* Hh = g_hbuf[src];
    int tid = threadIdx.x;           // 512 threads
    int bx = blockIdx.x;

    // ================= ac path =================
    if (bx >= DIST_BLOCKS) {
        int nl = tid >> 6, d = tid & 63;
        int i = (bx - DIST_BLOCKS) * 8 + nl;
        float (*hs)[64] = (float(*)[64])&His[0][0];   // reuse smem
        hs[nl][d] = Hh[i * 64 + d];
        __syncthreads();
        const float* W = convW + l * 128 * 64;
        float a = 0.0f;
#pragma unroll 8
        for (int e = 0; e < 64; e++)
            a = __fmaf_rn(hs[nl][e], W[e * 64 + d], a);
        g_s64[i * 64 + d] = a;
        return;
    }

    // ================= dist path =================
    int g = bx / NPAIRS;
    int idx = bx % NPAIRS;
    int ti = (int)((sqrtf(8.0f * (float)idx + 1.0f) - 1.0f) * 0.5f);
    while ((ti + 1) * (ti + 2) / 2 <= idx) ti++;
    while (ti * (ti + 1) / 2 > idx) ti--;
    int tj = idx - ti * (ti + 1) / 2;

    int i0 = ti * TM;
    int j0 = tj * TM;
    int base = g * NPG;
    int tx = tid & 31, ty = tid >> 5;
    float acc[8][4];
#pragma unroll
    for (int a = 0; a < 8; a++)
#pragma unroll
        for (int b = 0; b < 4; b++) acc[a][b] = 0.0f;

    float sacc = 0.0f;     // sq accumulator for threads < 256 (frozen serial chain)

    for (int kc = 0; kc < HDIM; kc += KC) {
        __syncthreads();
        for (int t = tid; t < TM * KC; t += 512) {
            int node = t >> 5;
            int k = t & 31;
            int gi = i0 + node;
            His[k][node] = (gi < NPG) ? Hh[(base + gi) * 64 + kc + k] : 0.0f;
            int gj = j0 + node;
            Hjs[k][node] = (gj < NPG) ? Hh[(base + gj) * 64 + kc + k] : 0.0f;
        }
        __syncthreads();
        // sq chain continuation over this chunk (k ascending -> global order)
        if (tid < 128) {
#pragma unroll 8
            for (int k = 0; k < KC; k++) {
                float v = His[k][tid];
                sacc = __fadd_rn(sacc, __fmul_rn(v, v));
            }
        } else if (tid < 256) {
#pragma unroll 8
            for (int k = 0; k < KC; k++) {
                float v = Hjs[k][tid - 128];
                sacc = __fadd_rn(sacc, __fmul_rn(v, v));
            }
        }
#pragma unroll
        for (int k = 0; k < KC; k++) {
            float av[8], bv[4];
            *(float4*)&av[0] = *(const float4*)&His[k][ty * 8];
            *(float4*)&av[4] = *(const float4*)&His[k][ty * 8 + 4];
            *(float4*)&bv[0] = *(const float4*)&Hjs[k][tx * 4];
#pragma unroll
            for (int a = 0; a < 8; a++)
#pragma unroll
                for (int b = 0; b < 4; b++)
                    acc[a][b] = __fmaf_rn(av[a], bv[b], acc[a][b]);
        }
    }

    if (tid < 128) sqi[tid] = sacc;
    else if (tid < 256) sqj[tid - 128] = sacc;
    __syncthreads();

    float si[8], sj[4];
#pragma unroll
    for (int a = 0; a < 8; a++) si[a] = sqi[ty * 8 + a];
#pragma unroll
    for (int b = 0; b < 4; b++) sj[b] = sqj[tx * 4 + b];

    float* d2g = g_d2 + (size_t)g * NPG * NPG;
#pragma unroll
    for (int a = 0; a < 8; a++) {
        int gi = i0 + ty * 8 + a;
        if (gi >= NPG) continue;
        int gj0 = j0 + tx * 4;
        float v0 = __fsub_rn(__fadd_rn(si[a], sj[0]), __fmul_rn(2.0f, acc[a][0]));
        float v1 = __fsub_rn(__fadd_rn(si[a], sj[1]), __fmul_rn(2.0f, acc[a][1]));
        float v2 = __fsub_rn(__fadd_rn(si[a], sj[2]), __fmul_rn(2.0f, acc[a][2]));
        float v3 = __fsub_rn(__fadd_rn(si[a], sj[3]), __fmul_rn(2.0f, acc[a][3]));
        if (gj0 + 3 < NPG) {
            float4 vv = make_float4(v0, v1, v2, v3);
            *(float4*)&d2g[gi * NPG + gj0] = vv;
        } else {
            if (gj0     < NPG) d2g[gi * NPG + gj0]     = v0;
            if (gj0 + 1 < NPG) d2g[gi * NPG + gj0 + 1] = v1;
            if (gj0 + 2 < NPG) d2g[gi * NPG + gj0 + 2] = v2;
            if (gj0 + 3 < NPG) d2g[gi * NPG + gj0 + 3] = v3;
        }
    }

    if (ti != tj) {
        float* Tr = &His[0][0];            // [128][33]
#pragma unroll 1
        for (int c = 0; c < 4; c++) {
            __syncthreads();
            if ((ty >> 2) == c) {
#pragma unroll
                for (int a = 0; a < 8; a++) {
                    int il = (ty * 8 + a) & 31;
#pragma unroll
                    for (int b = 0; b < 4; b++) {
                        float v = __fsub_rn(__fadd_rn(si[a], sj[b]), __fmul_rn(2.0f, acc[a][b]));
                        Tr[(tx * 4 + b) * 33 + il] = v;
                    }
                }
            }
            __syncthreads();
            for (int t = tid; t < 128 * 32; t += 512) {
                int jr = t >> 5, ic = t & 31;
                int gj = j0 + jr, gi = i0 + c * 32 + ic;
                if (gj < NPG && gi < NPG)
                    d2g[(size_t)gj * NPG + gi] = Tr[jr * 33 + ic];
            }
        }
    }
}

// ---------------- fused knn (tournament + redux) + edge MLP + BN + max aggr + residual ----------------
// R15 version (best measured). Phase A: per-warp tournament top-K (lane L owns
// j in [32L,32L+32), left-preferring tree), warp-min via two REDUX ops.
// Phase B: edge-MLP with bitwise-frozen serial ascending-k chains + exact BN order.
__global__ void agg_kernel(int src, const float* __restrict__ convW,
                           const float* __restrict__ convb,
                           const float* __restrict__ bn_g, const float* __restrict__ bn_b,
                           const float* __restrict__ bn_m, const float* __restrict__ bn_v,
                           int l) {
    union SmemU {
        unsigned tree[4 * 32 * 65];                       // 33280 B
        struct { float WbT[64][68]; float diff[4][KNN][64]; } m;  // 37888 B
    };
    __shared__ __align__(16) SmemU su;
    __shared__ int idxs[4][KNN];

    int tid = threadIdx.x;                 // 128
    int nl = tid >> 5, lane = tid & 31;
    int i = blockIdx.x * 4 + nl;
    int g = i / NPG, il = i % NPG;
    const float* Hh = g_hbuf[src];
    float* hdst = g_hbuf[src ^ 1];
    const float* W = convW + l * 128 * 64;

    // ================= Phase A: kNN tournament =================
    {
        const float* row = g_d2 + (size_t)g * NPG * NPG + (size_t)il * NPG;
        unsigned* tr = su.tree + nl * 32 * 65;   // [lane][node]: addr = lane*65 + node

#pragma unroll
        for (int q = 0; q < 8; q++) {
            int j = q * 128 + lane * 4;
            float4 r4;
            if (j + 3 < NPG) {
                r4 = *(const float4*)&row[j];
            } else {
                r4.x = (j     < NPG) ? row[j]     : 0.0f;
                r4.y = (j + 1 < NPG) ? row[j + 1] : 0.0f;
                r4.z = (j + 2 < NPG) ? row[j + 2] : 0.0f;
                r4.w = (j + 3 < NPG) ? row[j + 3] : 0.0f;
            }
            unsigned k0 = (j     < NPG) ? mono32(r4.x) : 0xFFFFFFFFu;
            unsigned k1 = (j + 1 < NPG) ? mono32(r4.y) : 0xFFFFFFFFu;
            unsigned k2 = (j + 2 < NPG) ? mono32(r4.z) : 0xFFFFFFFFu;
            unsigned k3 = (j + 3 < NPG) ? mono32(r4.w) : 0xFFFFFFFFu;
            int lp = j >> 5;
            int nd = 32 + (j & 31);
            unsigned* D = tr + lp * 65 + nd;
            D[0] = k0; D[1] = k1; D[2] = k2; D[3] = k3;
        }
        __syncwarp();

        unsigned* T = tr + lane * 65;
#pragma unroll
        for (int n = 31; n >= 1; n--) {
            unsigned a = T[2 * n], b = T[2 * n + 1];
            T[n] = (a <= b) ? a : b;
        }
        __syncwarp();

        for (int it = 0; it < KNN; it++) {
            unsigned rk = T[1];
            unsigned m = __reduce_min_sync(0xFFFFFFFFu, rk);
            unsigned prop = (rk == m) ? (unsigned)lane : 32u;
            unsigned wl = __reduce_min_sync(0xFFFFFFFFu, prop);
            if (lane == (int)wl) {
                int n = 1;
#pragma unroll
                for (int lev = 0; lev < 5; lev++) {
                    unsigned a = T[2 * n], b = T[2 * n + 1];
                    n = 2 * n + ((a <= b) ? 0 : 1);
                }
                int j = lane * 32 + (n - 32);
                idxs[nl][it] = g * NPG + j;
                T[n] = 0xFFFFFFFFu;
#pragma unroll
                for (int lev = 0; lev < 5; lev++) {
                    n >>= 1;
                    unsigned a = T[2 * n], b = T[2 * n + 1];
                    T[n] = (a <= b) ? a : b;
                }
            }
            __syncwarp();
        }
    }
    __syncthreads();   // all warps done with tree before union reuse

    // ================= Phase B: edge MLP (bitwise-frozen chains) =================
    for (int t = tid; t < 4096; t += 128) {
        int k = t >> 6, d = t & 63;
        su.m.WbT[d][k] = W[(64 + k) * 64 + d];
    }
    __syncthreads();

    float xi0 = Hh[i * 64 + lane];
    float xi1 = Hh[i * 64 + lane + 32];

#pragma unroll
    for (int nb = 0; nb < KNN; nb++) {
        const float* hj = Hh + idxs[nl][nb] * 64;
        su.m.diff[nl][nb][lane]      = __fsub_rn(hj[lane],      xi0);
        su.m.diff[nl][nb][lane + 32] = __fsub_rn(hj[lane + 32], xi1);
    }
    __syncwarp();

    float s0 = g_s64[i * 64 + lane];
    float s1 = g_s64[i * 64 + lane + 32];
    float acc0[KNN], acc1[KNN];
#pragma unroll
    for (int nb = 0; nb < KNN; nb++) { acc0[nb] = s0; acc1[nb] = s1; }

#pragma unroll 2
    for (int k4 = 0; k4 < 16; k4++) {
        float4 w0q = *(const float4*)&su.m.WbT[lane][k4 * 4];
        float4 w1q = *(const float4*)&su.m.WbT[lane + 32][k4 * 4];
#pragma unroll
        for (int nb = 0; nb < KNN; nb++) {
            float4 d4 = *(const float4*)&su.m.diff[nl][nb][k4 * 4];
            acc0[nb] = __fmaf_rn(d4.x, w0q.x, acc0[nb]);
            acc0[nb] = __fmaf_rn(d4.y, w0q.y, acc0[nb]);
            acc0[nb] = __fmaf_rn(d4.z, w0q.z, acc0[nb]);
            acc0[nb] = __fmaf_rn(d4.w, w0q.w, acc0[nb]);
            acc1[nb] = __fmaf_rn(d4.x, w1q.x, acc1[nb]);
            acc1[nb] = __fmaf_rn(d4.y, w1q.y, acc1[nb]);
            acc1[nb] = __fmaf_rn(d4.z, w1q.z, acc1[nb]);
            acc1[nb] = __fmaf_rn(d4.w, w1q.w, acc1[nb]);
        }
    }

    float bi0 = convb[l * 64 + lane],  bi1 = convb[l * 64 + lane + 32];
    float mm0 = bn_m[l * 64 + lane],   mm1 = bn_m[l * 64 + lane + 32];
    float bb0 = bn_b[l * 64 + lane],   bb1 = bn_b[l * 64 + lane + 32];
    float gg0 = bn_g[l * 64 + lane],   gg1 = bn_g[l * 64 + lane + 32];
    float rr0 = __fdiv_rn(1.0f, __fsqrt_rn(__fadd_rn(bn_v[l * 64 + lane],      1e-5f)));
    float rr1 = __fdiv_rn(1.0f, __fsqrt_rn(__fadd_rn(bn_v[l * 64 + lane + 32], 1e-5f)));
    float best0 = -FLT_MAX, best1 = -FLT_MAX;
#pragma unroll
    for (int nb = 0; nb < KNN; nb++) {
        float e0 = eluf(__fadd_rn(acc0[nb], bi0));
        float e1 = eluf(__fadd_rn(acc1[nb], bi1));
        float v0 = __fadd_rn(__fmul_rn(__fmul_rn(gg0, __fsub_rn(e0, mm0)), rr0), bb0);
        float v1 = __fadd_rn(__fmul_rn(__fmul_rn(gg1, __fsub_rn(e1, mm1)), rr1), bb1);
        best0 = fmaxf(best0, v0);
        best1 = fmaxf(best1, v1);
    }
    hdst[i * 64 + lane]      = __fadd_rn(best0, xi0);
    hdst[i * 64 + lane + 32] = __fadd_rn(best1, xi1);
}

// ---------------- output heads: 32 nodes/block, weights staged in smem ----------------
__global__ void heads_kernel(int src,
                             const float* __restrict__ oW1, const float* __restrict__ ob1,
                             const float* __restrict__ oW2, const float* __restrict__ ob2,
                             const float* __restrict__ oW3, const float* __restrict__ ob3,
                             const float* __restrict__ spW1, const float* __restrict__ spb1,
                             const float* __restrict__ spW2, const float* __restrict__ spb2,
                             const float* __restrict__ spW3, const float* __restrict__ spb3,
                             float* __restrict__ out, int out_size, int N) {
    __shared__ float sW1[64 * 64], sW2[64 * 32], sW3[32 * 8];
    __shared__ float sb1v[64], sb2v[32], sb3v[8];
    __shared__ float hr[32][65], t1[32][65], t2[32][33];
    int tid = threadIdx.x;               // 256
    int i0 = blockIdx.x * 32;
    const float* Hh = g_hbuf[src];

    for (int t = tid; t < 32 * 64; t += 256)
        hr[t >> 6][t & 63] = Hh[(i0 + (t >> 6)) * 64 + (t & 63)];

    int node = tid >> 3, slot = tid & 7;

    for (int head = 0; head < 2; head++) {
        const float* w1 = head == 0 ? oW1 : spW1;
        const float* w2 = head == 0 ? oW2 : spW2;
        const float* w3 = head == 0 ? oW3 : spW3;
        const float* c1 = head == 0 ? ob1 : spb1;
        const float* c2 = head == 0 ? ob2 : spb2;
        const float* c3 = head == 0 ? ob3 : spb3;
        int w3n = head == 0 ? 256 : 32;

        for (int t = tid; t < 4096; t += 256) sW1[t] = w1[t];
        for (int t = tid; t < 2048; t += 256) sW2[t] = w2[t];
        if (tid < 256 && tid < w3n) sW3[tid] = w3[tid];
        if (tid < 64) sb1v[tid] = c1[tid];
        if (tid < 32) sb2v[tid] = c2[tid];
        if (tid < 8)  sb3v[tid] = (head == 0) ? c3[tid] : (tid == 0 ? c3[0] : 0.0f);
        __syncthreads();

#pragma unroll
        for (int oo = 0; oo < 8; oo++) {
            int o = slot * 8 + oo;
            float s = 0.0f;
#pragma unroll 8
            for (int e = 0; e < 64; e++) s = __fmaf_rn(hr[node][e], sW1[e * 64 + o], s);
            t1[node][o] = eluf(__fadd_rn(s, sb1v[o]));
        }
        __syncthreads();
#pragma unroll
        for (int oo = 0; oo < 4; oo++) {
            int o = slot * 4 + oo;
            float s = 0.0f;
#pragma unroll 8
            for (int e = 0; e < 64; e++) s = __fmaf_rn(t1[node][e], sW2[e * 32 + o], s);
            t2[node][o] = eluf(__fadd_rn(s, sb2v[o]));
        }
        __syncthreads();
        if (head == 0) {
            int o = slot;
            float s = 0.0f;
#pragma unroll
            for (int e = 0; e < 32; e++) s = __fmaf_rn(t2[node][e], sW3[e * 8 + o], s);
            out[(i0 + node) * 8 + o] = __fadd_rn(s, sb3v[o]);
        } else {
            if (slot == 0) {
                float s = 0.0f;
#pragma unroll
                for (int e = 0; e < 32; e++) s = __fmaf_rn(t2[node][e], sW3[e], s);
                s = __fadd_rn(s, sb3v[0]);
                int i = i0 + node;
                int off_sp = N * 8;
                if (off_sp + i < out_size) out[off_sp + i] = s;
                int off_b = N * 9;
                if (off_b + i < out_size) out[off_b + i] = (float)(i / NPG);
            }
        }
        __syncthreads();
    }
}

// ---------------- host launcher ----------------
extern "C" void kernel_launch(void* const* d_in, const int* in_sizes, int n_in,
                              void* d_out, int out_size) {
    const float* x     = (const float*)d_in[0];
    const float* lcW1  = (const float*)d_in[2];
    const float* lcb1  = (const float*)d_in[3];
    const float* lcW2  = (const float*)d_in[4];
    const float* lcb2  = (const float*)d_in[5];
    const float* convW = (const float*)d_in[6];
    const float* convb = (const float*)d_in[7];
    const float* bn_g  = (const float*)d_in[8];
    const float* bn_b  = (const float*)d_in[9];
    const float* bn_m  = (const float*)d_in[10];
    const float* bn_v  = (const float*)d_in[11];
    const float* outW1 = (const float*)d_in[12];
    const float* outb1 = (const float*)d_in[13];
    const float* outW2 = (const float*)d_in[14];
    const float* outb2 = (const float*)d_in[15];
    const float* outW3 = (const float*)d_in[16];
    const float* outb3 = (const float*)d_in[17];
    const float* spW1  = (const float*)d_in[18];
    const float* spb1  = (const float*)d_in[19];
    const float* spW2  = (const float*)d_in[20];
    const float* spb2  = (const float*)d_in[21];
    const float* spW3  = (const float*)d_in[22];
    const float* spb3  = (const float*)d_in[23];

    const int N = in_sizes[0] / 8;          // 16000

    lc_kernel<<<N / 32, 256>>>(x, lcW1, lcb1, lcW2, lcb2);

    int src = 0;
    for (int l = 0; l < LAYERS; l++) {
        dist_ac_kernel<<<DIST_BLOCKS + N / 8, 512>>>(src, convW, l);
        agg_kernel<<<N / 4, 128>>>(src, convW, convb, bn_g, bn_b, bn_m, bn_v, l);
        src ^= 1;
    }

    heads_kernel<<<N / 32, 256>>>(src, outW1, outb1, outW2, outb2, outW3, outb3,
                                  spW1, spb1, spW2, spb2, spW3, spb3,
                                  (float*)d_out, out_size, N);
}